// round 10
// baseline (speedup 1.0000x reference)
#include <cuda_runtime.h>

#define NCLS 20
#define NSUP 100
#define NQRY 300
#define DDIM 640
#define NTASK 256
#define THREADS 256
#define ROW16 (DDIM / 4)      // 160 16-byte elements per row
#define NCHUNK (DDIM / 32)    // 20 chunks: 8 lanes x 4 floats
#define NGRP (NQRY / 4)       // 75 groups: 4 queries per warp-group (1 per subgroup)

__device__ float g_task_loss[NTASK];
__device__ unsigned int g_ticket = 0;

__device__ __forceinline__ unsigned long long ffma2(unsigned long long a,
                                                    unsigned long long b,
                                                    unsigned long long c) {
    unsigned long long d;
    asm("fma.rn.f32x2 %0, %1, %2, %3;" : "=l"(d) : "l"(a), "l"(b), "l"(c));
    return d;
}
__device__ __forceinline__ unsigned long long fadd2(unsigned long long a,
                                                    unsigned long long b) {
    unsigned long long d;
    asm("add.rn.f32x2 %0, %1, %2;" : "=l"(d) : "l"(a), "l"(b));
    return d;
}
__device__ __forceinline__ float2 unpk2(unsigned long long v) {
    float lo, hi;
    asm("mov.b64 {%0, %1}, %2;" : "=f"(lo), "=f"(hi) : "l"(v));
    return make_float2(lo, hi);
}

extern __shared__ float smem_raw[];

__global__ __launch_bounds__(THREADS, 2)
void proto_loss_kernel(const float* __restrict__ sup,
                       const float* __restrict__ qry,
                       const int* __restrict__ tsup,
                       const int* __restrict__ tqry,
                       float* __restrict__ out) {
    float* proto  = smem_raw;                    // [20][640]
    float* psq    = proto + NCLS * DDIM;         // [20]
    float* wsum   = psq + NCLS;                  // [8]
    int*   counts = (int*)(wsum + 8);            // [20]
    int*   labels = counts + NCLS;               // [100]
    int*   tqs    = labels + NSUP;               // [300]
    int*   flag   = tqs + NQRY;                  // [1]

    const int b    = blockIdx.x;
    const int tid  = threadIdx.x;
    const int lane = tid & 31;
    const int wid  = tid >> 5;
    const int sub  = (lane >> 3);   // subgroup 0..3
    const int sl   = lane & 7;      // lane within subgroup

    // ======== Phase 1: prototypes ========
    for (int i = tid; i < NCLS * DDIM; i += THREADS) proto[i] = 0.f;
    if (tid < NCLS) counts[tid] = 0;
    if (tid < NSUP) labels[tid] = tsup[b * NSUP + tid];
    for (int i = tid; i < NQRY; i += THREADS) tqs[i] = tqry[b * NQRY + i];
    __syncthreads();
    if (tid < NSUP) atomicAdd(&counts[labels[tid]], 1);

    const float* supb = sup + (size_t)b * NSUP * DDIM;
    for (int d = tid; d < DDIM; d += THREADS) {
        int cur = labels[0];
        float run = 0.f;
        #pragma unroll 5
        for (int s = 0; s < NSUP; s++) {
            int L = labels[s];
            if (L != cur) { proto[cur * DDIM + d] += run; run = 0.f; cur = L; }
            run += supb[s * DDIM + d];
        }
        proto[cur * DDIM + d] += run;
    }
    __syncthreads();

    #pragma unroll
    for (int c = 0; c < NCLS; c++) {
        float inv = 1.f / (float)counts[c];
        for (int d = tid; d < DDIM; d += THREADS) proto[c * DDIM + d] *= inv;
    }
    __syncthreads();

    for (int c = wid; c < NCLS; c += 8) {
        float v = 0.f;
        for (int d = lane; d < DDIM; d += 32) {
            float p = proto[c * DDIM + d];
            v = fmaf(p, p, v);
        }
        #pragma unroll
        for (int o = 16; o; o >>= 1) v += __shfl_xor_sync(0xffffffffu, v, o);
        if (!lane) psq[c] = v;
    }
    __syncthreads();

    // ======== Phase 2: query distances + log-softmax ========
    const ulonglong2* q2 = (const ulonglong2*)(qry + (size_t)b * NQRY * DDIM);
    const ulonglong2* p2base = (const ulonglong2*)proto;
    float nll = 0.f;

    for (int g = wid; g < NGRP; g += 8) {
        const int q = g * 4 + sub;   // this subgroup's query (always < 300)
        const ulonglong2* qrow = q2 + (size_t)q * ROW16 + sl;
        const ulonglong2* prow = p2base + sl;

        unsigned long long acc[NCLS];
        #pragma unroll
        for (int c = 0; c < NCLS; c++) acc[c] = 0ull;

        // ptxas batches the 5 LDGs of each unroll body itself (regs now free)
        #pragma unroll 5
        for (int ch = 0; ch < NCHUNK; ch++) {
            ulonglong2 va = qrow[ch * 8];
            #pragma unroll
            for (int c = 0; c < NCLS; c++) {
                ulonglong2 pv = prow[c * ROW16 + ch * 8];   // broadcast across subgroups
                acc[c] = ffma2(va.x, pv.x, acc[c]);
                acc[c] = ffma2(va.y, pv.y, acc[c]);
            }
        }

        // 3-round butterfly within the 8-lane subgroup
        #pragma unroll
        for (int c = 0; c < NCLS; c++) {
            #pragma unroll
            for (int o = 4; o; o >>= 1)
                acc[c] = fadd2(acc[c], __shfl_xor_sync(0xffffffffu, acc[c], o));
        }

        // ---- two-pass epilogue: no sv[] array, recompute from live accs ----
        {
            const int tgt = tqs[q];
            float m = -1e30f, st = 0.f;
            #pragma unroll
            for (int c = 0; c < NCLS; c++) {
                float2 x = unpk2(acc[c]);
                float sv = fmaf(2.f, x.x + x.y, -psq[c]);   // -dist + const(q)
                m = fmaxf(m, sv);
                if (c == tgt) st = sv;
            }
            float sum = 0.f;
            #pragma unroll
            for (int c = 0; c < NCLS; c++) {
                float2 x = unpk2(acc[c]);
                float sv = fmaf(2.f, x.x + x.y, -psq[c]);
                sum += __expf(sv - m);
            }
            nll += (m + __logf(sum)) - st;
        }
    }

    // all 8 lanes of a subgroup hold identical nll; full-warp sum / 8 is exact
    #pragma unroll
    for (int o = 16; o; o >>= 1) nll += __shfl_xor_sync(0xffffffffu, nll, o);
    nll *= 0.125f;

    if (!lane) wsum[wid] = nll;
    __syncthreads();
    if (tid == 0) {
        float t = 0.f;
        #pragma unroll
        for (int w = 0; w < 8; w++) t += wsum[w];
        g_task_loss[b] = t * (1.f / (float)NQRY);
        __threadfence();
        unsigned int v = atomicAdd(&g_ticket, 1u);
        *flag = ((v + 1u) % NTASK == 0u) ? 1 : 0;
    }
    __syncthreads();

    // last-arriving CTA performs the deterministic final reduction
    if (*flag) {
        __threadfence();
        float x = __ldcg(&g_task_loss[tid]);
        float* red = proto;   // reuse smem
        red[tid] = x;
        __syncthreads();
        #pragma unroll
        for (int off = 128; off; off >>= 1) {
            if (tid < off) red[tid] += red[tid + off];
            __syncthreads();
        }
        if (tid == 0) out[0] = red[0] * (1.f / (float)NTASK);
    }
}

extern "C" void kernel_launch(void* const* d_in, const int* in_sizes, int n_in,
                              void* d_out, int out_size) {
    const float* sup = (const float*)d_in[0];
    const float* qry = (const float*)d_in[1];
    const int*   ts  = (const int*)d_in[2];
    const int*   tq  = (const int*)d_in[3];
    float* out = (float*)d_out;

    const size_t SMEM = (size_t)(NCLS * DDIM + NCLS + 8) * sizeof(float)
                      + (size_t)(NCLS + NSUP + NQRY + 1) * sizeof(int);
    cudaFuncSetAttribute(proto_loss_kernel,
                         cudaFuncAttributeMaxDynamicSharedMemorySize, (int)SMEM);
    proto_loss_kernel<<<NTASK, THREADS, SMEM>>>(sup, qry, ts, tq, out);
}

// round 11
// speedup vs baseline: 1.6698x; 1.6698x over previous
#include <cuda_runtime.h>

#define NCLS 20
#define NHALF 10
#define NSUP 100
#define NQRY 300
#define DDIM 640
#define NTASK 256
#define THREADS 256
#define ROW16 (DDIM / 4)      // 160 16-byte elements per row
#define NCHUNK (DDIM / 32)    // 20 chunks: 8 lanes x 4 floats
#define NGRP 38               // ceil(300/8): 8 queries per warp-group (2 per subgroup)

__device__ float g_task_loss[NTASK];
__device__ unsigned int g_ticket = 0;

__device__ __forceinline__ unsigned long long ffma2(unsigned long long a,
                                                    unsigned long long b,
                                                    unsigned long long c) {
    unsigned long long d;
    asm("fma.rn.f32x2 %0, %1, %2, %3;" : "=l"(d) : "l"(a), "l"(b), "l"(c));
    return d;
}
__device__ __forceinline__ unsigned long long fadd2(unsigned long long a,
                                                    unsigned long long b) {
    unsigned long long d;
    asm("add.rn.f32x2 %0, %1, %2;" : "=l"(d) : "l"(a), "l"(b));
    return d;
}
__device__ __forceinline__ float2 unpk2(unsigned long long v) {
    float lo, hi;
    asm("mov.b64 {%0, %1}, %2;" : "=f"(lo), "=f"(hi) : "l"(v));
    return make_float2(lo, hi);
}

extern __shared__ float smem_raw[];

__global__ __launch_bounds__(THREADS, 2)
void proto_loss_kernel(const float* __restrict__ sup,
                       const float* __restrict__ qry,
                       const int* __restrict__ tsup,
                       const int* __restrict__ tqry,
                       float* __restrict__ out) {
    float* proto  = smem_raw;                    // [20][640]
    float* psq    = proto + NCLS * DDIM;         // [20]
    float* wsum   = psq + NCLS;                  // [8]
    int*   counts = (int*)(wsum + 8);            // [20]
    int*   labels = counts + NCLS;               // [100]
    int*   tqs    = labels + NSUP;               // [300]
    int*   flag   = tqs + NQRY;                  // [1]

    const int b    = blockIdx.x;
    const int tid  = threadIdx.x;
    const int lane = tid & 31;
    const int wid  = tid >> 5;
    const int sub  = (lane >> 3);   // subgroup 0..3
    const int sl   = lane & 7;      // lane within subgroup

    // ======== Phase 1: prototypes (float4 path) ========
    for (int i = tid; i < NCLS * DDIM; i += THREADS) proto[i] = 0.f;
    if (tid < NCLS) counts[tid] = 0;
    if (tid < NSUP) labels[tid] = tsup[b * NSUP + tid];
    for (int i = tid; i < NQRY; i += THREADS) tqs[i] = tqry[b * NQRY + i];
    __syncthreads();
    if (tid < NSUP) atomicAdd(&counts[labels[tid]], 1);

    if (tid < ROW16) {   // 160 threads: one float4 column each
        const float4* sup4 = (const float4*)(sup + (size_t)b * NSUP * DDIM);
        float4* proto4 = (float4*)proto;
        int cur = labels[0];
        float4 run = make_float4(0.f, 0.f, 0.f, 0.f);
        #pragma unroll 5
        for (int s = 0; s < NSUP; s++) {
            int L = labels[s];
            if (L != cur) {
                float4 p = proto4[cur * ROW16 + tid];
                p.x += run.x; p.y += run.y; p.z += run.z; p.w += run.w;
                proto4[cur * ROW16 + tid] = p;
                run = make_float4(0.f, 0.f, 0.f, 0.f);
                cur = L;
            }
            float4 v = sup4[s * ROW16 + tid];
            run.x += v.x; run.y += v.y; run.z += v.z; run.w += v.w;
        }
        float4 p = proto4[cur * ROW16 + tid];
        p.x += run.x; p.y += run.y; p.z += run.z; p.w += run.w;
        proto4[cur * ROW16 + tid] = p;
    }
    __syncthreads();

    #pragma unroll
    for (int c = 0; c < NCLS; c++) {
        float inv = 1.f / (float)counts[c];
        for (int d = tid; d < DDIM; d += THREADS) proto[c * DDIM + d] *= inv;
    }
    __syncthreads();

    for (int c = wid; c < NCLS; c += 8) {
        float v = 0.f;
        for (int d = lane; d < DDIM; d += 32) {
            float p = proto[c * DDIM + d];
            v = fmaf(p, p, v);
        }
        #pragma unroll
        for (int o = 16; o; o >>= 1) v += __shfl_xor_sync(0xffffffffu, v, o);
        if (!lane) psq[c] = v;
    }
    __syncthreads();

    // ======== Phase 2: 2 queries/lane, classes split 10+10 ========
    const ulonglong2* q2 = (const ulonglong2*)(qry + (size_t)b * NQRY * DDIM);
    const ulonglong2* prow = (const ulonglong2*)proto + sl;
    float nll = 0.f;

    for (int g = wid; g < NGRP; g += 8) {
        const int q0 = g * 8 + sub * 2;
        const int q1 = q0 + 1;
        const int q0c = q0 < NQRY ? q0 : NQRY - 1;
        const int q1c = q1 < NQRY ? q1 : NQRY - 1;
        const ulonglong2* qrow0 = q2 + (size_t)q0c * ROW16 + sl;
        const ulonglong2* qrow1 = q2 + (size_t)q1c * ROW16 + sl;

        float sv[2][NCLS];

        #pragma unroll
        for (int half = 0; half < 2; half++) {
            const int cb = half * NHALF;
            unsigned long long a0[NHALF], a1[NHALF];
            #pragma unroll
            for (int c = 0; c < NHALF; c++) { a0[c] = 0ull; a1[c] = 0ull; }

            #pragma unroll 5
            for (int ch = 0; ch < NCHUNK; ch++) {
                ulonglong2 va = qrow0[ch * 8];
                ulonglong2 vb = qrow1[ch * 8];
                #pragma unroll
                for (int c = 0; c < NHALF; c++) {
                    ulonglong2 pv = prow[(cb + c) * ROW16 + ch * 8];
                    a0[c] = ffma2(va.x, pv.x, a0[c]);
                    a0[c] = ffma2(va.y, pv.y, a0[c]);
                    a1[c] = ffma2(vb.x, pv.x, a1[c]);
                    a1[c] = ffma2(vb.y, pv.y, a1[c]);
                }
            }

            // 3-round butterfly within the 8-lane subgroup
            #pragma unroll
            for (int c = 0; c < NHALF; c++) {
                #pragma unroll
                for (int o = 4; o; o >>= 1) {
                    a0[c] = fadd2(a0[c], __shfl_xor_sync(0xffffffffu, a0[c], o));
                    a1[c] = fadd2(a1[c], __shfl_xor_sync(0xffffffffu, a1[c], o));
                }
            }
            #pragma unroll
            for (int c = 0; c < NHALF; c++) {
                float2 x0 = unpk2(a0[c]);
                float2 x1 = unpk2(a1[c]);
                sv[0][cb + c] = fmaf(2.f, x0.x + x0.y, -psq[cb + c]);  // -dist+const
                sv[1][cb + c] = fmaf(2.f, x1.x + x1.y, -psq[cb + c]);
            }
        }

        // epilogue: 2 queries, sv already in registers
        #pragma unroll
        for (int qi = 0; qi < 2; qi++) {
            const int q = q0 + qi;
            const int tgt = tqs[q < NQRY ? q : NQRY - 1];
            float m = -1e30f, st = 0.f;
            #pragma unroll
            for (int c = 0; c < NCLS; c++) {
                m = fmaxf(m, sv[qi][c]);
                if (c == tgt) st = sv[qi][c];
            }
            float sum = 0.f;
            #pragma unroll
            for (int c = 0; c < NCLS; c++) sum += __expf(sv[qi][c] - m);
            if (q < NQRY) nll += (m + __logf(sum)) - st;
        }
    }

    // all 8 lanes of a subgroup hold identical nll; full-warp sum / 8 is exact
    #pragma unroll
    for (int o = 16; o; o >>= 1) nll += __shfl_xor_sync(0xffffffffu, nll, o);
    nll *= 0.125f;

    if (!lane) wsum[wid] = nll;
    __syncthreads();
    if (tid == 0) {
        float t = 0.f;
        #pragma unroll
        for (int w = 0; w < 8; w++) t += wsum[w];
        g_task_loss[b] = t * (1.f / (float)NQRY);
        __threadfence();
        unsigned int v = atomicAdd(&g_ticket, 1u);
        *flag = ((v + 1u) % NTASK == 0u) ? 1 : 0;
    }
    __syncthreads();

    // last-arriving CTA performs the deterministic final reduction
    if (*flag) {
        __threadfence();
        float x = __ldcg(&g_task_loss[tid]);
        float* red = proto;   // reuse smem
        red[tid] = x;
        __syncthreads();
        #pragma unroll
        for (int off = 128; off; off >>= 1) {
            if (tid < off) red[tid] += red[tid + off];
            __syncthreads();
        }
        if (tid == 0) out[0] = red[0] * (1.f / (float)NTASK);
    }
}

extern "C" void kernel_launch(void* const* d_in, const int* in_sizes, int n_in,
                              void* d_out, int out_size) {
    const float* sup = (const float*)d_in[0];
    const float* qry = (const float*)d_in[1];
    const int*   ts  = (const int*)d_in[2];
    const int*   tq  = (const int*)d_in[3];
    float* out = (float*)d_out;

    const size_t SMEM = (size_t)(NCLS * DDIM + NCLS + 8) * sizeof(float)
                      + (size_t)(NCLS + NSUP + NQRY + 1) * sizeof(int);
    cudaFuncSetAttribute(proto_loss_kernel,
                         cudaFuncAttributeMaxDynamicSharedMemorySize, (int)SMEM);
    proto_loss_kernel<<<NTASK, THREADS, SMEM>>>(sup, qry, ts, tq, out);
}